// round 3
// baseline (speedup 1.0000x reference)
#include <cuda_runtime.h>
#include <math.h>

// Problem constants
#define Bn 65536
#define Dn 256
#define Kn 1024

// Tiling
#define ROWS 128          // rows per block
#define KT   64           // codes per k-tile
#define STRIDE 258        // padded row stride in floats (conflict-free LDS)
#define NBLK (Bn / ROWS)  // 512 blocks

// Scratch (no allocations allowed -> __device__ globals)
__device__ float g_sw[Kn];        // sum(W^2) per code
__device__ int   g_counts[Kn];    // usage histogram
__device__ float g_partial[NBLK]; // per-block sum of (q-x)^2

typedef unsigned long long ull;

__device__ __forceinline__ void upk(ull v, float& a, float& b) {
    asm("mov.b64 {%0,%1}, %2;" : "=f"(a), "=f"(b) : "l"(v));
}
// Packed dual-FMA: 2x fp32 FMA per issue (sm_100+ f32x2 pipe)
__device__ __forceinline__ void ffma2(ull& acc, ull x, ull w) {
    asm("fma.rn.f32x2 %0, %1, %2, %0;" : "+l"(acc) : "l"(x), "l"(w));
}

// ---------------------------------------------------------------------------
// prep: zero histogram, compute sum(W^2) per code
// grid 64 x 256 -> 16384 threads, 16 threads (half-warp) per code
// ---------------------------------------------------------------------------
__global__ void vq_prep(const float* __restrict__ W) {
    int g = blockIdx.x * blockDim.x + threadIdx.x;
    int code = g >> 4;
    int l = g & 15;
    const float* wr = W + (size_t)code * Dn + l * 16;
    float s = 0.f;
#pragma unroll
    for (int t = 0; t < 16; t++) { float v = wr[t]; s += v * v; }
#pragma unroll
    for (int o = 8; o; o >>= 1) s += __shfl_xor_sync(0xffffffffu, s, o, 16);
    if (l == 0) g_sw[code] = s;
    if (g < Kn) g_counts[g] = 0;
}

// ---------------------------------------------------------------------------
// main: fused distance GEMM + argmin + gather/quantize + loss partials
// block = 256 threads, tile = 128 rows x (all 1024 codes in 16 tiles of 64)
// thread micro-tile: 8 rows x 4 codes, packed f32x2 accumulators
// ---------------------------------------------------------------------------
__global__ __launch_bounds__(256, 1)
void vq_main(const float* __restrict__ X, const float* __restrict__ W,
             float* __restrict__ out) {
    extern __shared__ float sm[];
    float* Xs = sm;                            // [ROWS][STRIDE]
    float* Ws = sm + ROWS * STRIDE;            // [KT][STRIDE]
    int*   bIdx = (int*)(sm + (ROWS + KT) * STRIDE); // [ROWS]
    float* red  = (float*)(bIdx + ROWS);       // [8]

    const int tid = threadIdx.x;
    const int tx = tid & 15;     // code lane (16)
    const int ty = tid >> 4;     // row lane  (16)
    const int R0 = blockIdx.x * ROWS;

    // ---- load X tile (coalesced global, float2 smem stores) ----
    {
        const float4* Xg = (const float4*)(X + (size_t)R0 * Dn);
        for (int idx = tid; idx < ROWS * (Dn / 4); idx += 256) {
            int r = idx >> 6, c4 = idx & 63;
            float4 v = Xg[r * (Dn / 4) + c4];
            float2* d2 = (float2*)(Xs + r * STRIDE + c4 * 4);  // 8B aligned
            d2[0] = make_float2(v.x, v.y);
            d2[1] = make_float2(v.z, v.w);
        }
    }
    __syncthreads();

    // ---- per-row sum(x^2), reduced across the 16 code-lanes ----
    float sx[8];
#pragma unroll
    for (int i = 0; i < 8; i++) {
        int r = ty + 16 * i;
        const float* xr = Xs + r * STRIDE + tx * 16;
        float s = 0.f;
#pragma unroll
        for (int t = 0; t < 16; t++) s += xr[t] * xr[t];
#pragma unroll
        for (int o = 8; o; o >>= 1) s += __shfl_xor_sync(0xffffffffu, s, o, 16);
        sx[i] = s;
    }

    float bestv[8];
    int   besti[8];
#pragma unroll
    for (int i = 0; i < 8; i++) { bestv[i] = 3.0e38f; besti[i] = 0x7fffffff; }

    for (int kt = 0; kt < Kn / KT; ++kt) {
        const int C0 = kt * KT;
        // ---- load W tile ----
        {
            const float4* Wg4 = (const float4*)(W + (size_t)C0 * Dn);
            for (int idx = tid; idx < KT * (Dn / 4); idx += 256) {
                int c = idx >> 6, c4 = idx & 63;
                float4 v = Wg4[c * (Dn / 4) + c4];
                float2* d2 = (float2*)(Ws + c * STRIDE + c4 * 4);
                d2[0] = make_float2(v.x, v.y);
                d2[1] = make_float2(v.z, v.w);
            }
        }
        __syncthreads();

        ull acc[8][4];
#pragma unroll
        for (int i = 0; i < 8; i++)
#pragma unroll
            for (int j = 0; j < 4; j++) acc[i][j] = 0ull;  // packed {0.f,0.f}

        const float* xb = Xs + ty * STRIDE;
        const float* wb = Ws + tx * STRIDE;
#pragma unroll 2
        for (int dp = 0; dp < Dn / 2; ++dp) {
            ull wv[4], xv[8];
#pragma unroll
            for (int j = 0; j < 4; j++)
                wv[j] = *(const ull*)(wb + (16 * j) * STRIDE + 2 * dp);
#pragma unroll
            for (int i = 0; i < 8; i++)
                xv[i] = *(const ull*)(xb + (16 * i) * STRIDE + 2 * dp);
#pragma unroll
            for (int i = 0; i < 8; i++)
#pragma unroll
                for (int j = 0; j < 4; j++) ffma2(acc[i][j], xv[i], wv[j]);
        }
        __syncthreads();  // Ws reused next tile

        // ---- argmin update: dist = (sx + sw) - 2*dot  (ref rounding assoc.) ----
        float swc[4];
#pragma unroll
        for (int j = 0; j < 4; j++) swc[j] = g_sw[C0 + tx + 16 * j];
#pragma unroll
        for (int i = 0; i < 8; i++) {
#pragma unroll
            for (int j = 0; j < 4; j++) {
                float a, b;
                upk(acc[i][j], a, b);
                float dot = a + b;
                float dist = (sx[i] + swc[j]) - 2.0f * dot;
                int c = C0 + tx + 16 * j;
                if (dist < bestv[i] || (dist == bestv[i] && c < besti[i])) {
                    bestv[i] = dist; besti[i] = c;
                }
            }
        }
    }

    // ---- reduce argmin across the 16 code-lanes (first-min tie-break) ----
#pragma unroll
    for (int i = 0; i < 8; i++) {
        float v = bestv[i];
        int   ix = besti[i];
#pragma unroll
        for (int o = 8; o; o >>= 1) {
            float ov = __shfl_xor_sync(0xffffffffu, v, o, 16);
            int   oi = __shfl_xor_sync(0xffffffffu, ix, o, 16);
            if (ov < v || (ov == v && oi < ix)) { v = ov; ix = oi; }
        }
        if (tx == 0) {
            bIdx[ty + 16 * i] = ix;
            atomicAdd(&g_counts[ix], 1);
        }
    }
    __syncthreads();

    // ---- epilogue: quantized_st = x + (W[idx]-x); accumulate (q-x)^2 ----
    float lsum = 0.f;
    for (int r = 0; r < ROWS; ++r) {
        int   wi = bIdx[r];                 // smem broadcast
        float xv = Xs[r * STRIDE + tid];    // conflict-free (consecutive lanes)
        float wv = W[(size_t)wi * Dn + tid];// coalesced, L2-resident
        float dq = wv - xv;
        out[(size_t)(R0 + r) * Dn + tid] = xv + dq;
        lsum += dq * dq;
    }
#pragma unroll
    for (int o = 16; o; o >>= 1) lsum += __shfl_xor_sync(0xffffffffu, lsum, o);
    if ((tid & 31) == 0) red[tid >> 5] = lsum;
    __syncthreads();
    if (tid == 0) {
        float s = 0.f;
#pragma unroll
        for (int w = 0; w < 8; w++) s += red[w];
        g_partial[blockIdx.x] = s;  // deterministic fixed-order partial
    }
}

// ---------------------------------------------------------------------------
// final: reduce loss partials (double), entropy -> perplexity, write scalars
// ---------------------------------------------------------------------------
__global__ void vq_final(float* __restrict__ out, long long out_size) {
    __shared__ double sd[512];
    int tid = threadIdx.x;  // 512 threads

    double s = (double)g_partial[tid];  // NBLK == 512
    double e = 0.0;
    for (int c = tid; c < Kn; c += 512) {
        double p = (double)g_counts[c] / 65536.0;
        e += p * log(p + 1e-10);
    }

    sd[tid] = s;
    __syncthreads();
    for (int o = 256; o; o >>= 1) { if (tid < o) sd[tid] += sd[tid + o]; __syncthreads(); }
    double tot = sd[0];
    __syncthreads();
    sd[tid] = e;
    __syncthreads();
    for (int o = 256; o; o >>= 1) { if (tid < o) sd[tid] += sd[tid + o]; __syncthreads(); }

    if (tid == 0 && out_size >= (long long)Bn * Dn + 2) {
        double m = tot / ((double)Bn * (double)Dn);
        float mf = (float)m;
        float loss = mf + 0.25f * mf;          // q_latent + 0.25*e_latent (equal values)
        out[(size_t)Bn * Dn]     = loss;
        out[(size_t)Bn * Dn + 1] = (float)exp(-sd[0]);
    }
}

// ---------------------------------------------------------------------------
extern "C" void kernel_launch(void* const* d_in, const int* in_sizes, int n_in,
                              void* d_out, int out_size) {
    const float* A  = (const float*)d_in[0];
    const float* Bp = (const float*)d_in[1];
    const float* X;
    const float* W;
    if (in_sizes[0] == Bn * Dn) { X = A;  W = Bp; }
    else                        { X = Bp; W = A;  }
    float* out = (float*)d_out;

    const int smem_bytes = (ROWS + KT) * STRIDE * 4 + ROWS * 4 + 8 * 4;
    cudaFuncSetAttribute(vq_main, cudaFuncAttributeMaxDynamicSharedMemorySize,
                         smem_bytes);

    vq_prep<<<64, 256>>>(W);
    vq_main<<<NBLK, 256, smem_bytes>>>(X, W, out);
    vq_final<<<1, 512>>>(out, (long long)out_size);
}

// round 11
// speedup vs baseline: 1.1939x; 1.1939x over previous
#include <cuda_runtime.h>
#include <math.h>

// Problem constants
#define Bn 65536
#define Dn 256
#define Kn 1024

#define ROWS 128                 // rows (M) per CTA
#define NBLK (Bn / ROWS)         // 512 CTAs
#define NTILE 64                 // codes per n-tile
#define NCHUNKS 32               // 16 n-tiles x 2 k-halves
#define XS_STR 260               // floats: X row stride (ldmatrix conflict-free)
#define BS_STR 132               // floats: B chunk row stride (khalf = 128 dims)
#define TAU 1e-3f                // >= 2x worst-case tf32 truncation per distance

// vq_main smem offsets (bytes)
#define OFF_XS 0
#define XS_BYTES (ROWS * XS_STR * 4)            // 133120
#define OFF_B  XS_BYTES
#define B_BYTES (NTILE * BS_STR * 4)            // 33792 per buffer
#define OFF_SW (OFF_B + 2 * B_BYTES)            // 200704
#define OFF_B1 (OFF_SW + 4096)                  // 204800 (128 ull)
#define OFF_B2 (OFF_B1 + 1024)                  // 205824 (128 ull)
#define SMEM_MAIN (OFF_B2 + 1024)               // 206848

// vq_fallback smem offsets
#define FB_ROWS 32
#define FB_XS 0                                  // 32*260*4 = 33280
#define FB_WS 33280                              // 64*260*4 = 66560
#define FB_SW 99840                              // 4096
#define FB_SX 103936                             // 128
#define FB_RID 104064                            // 128
#define SMEM_FB 104192

// Scratch (no allocations allowed)
__device__ float g_sw[Kn];
__device__ int   g_counts[Kn];
__device__ float g_partial[NBLK];
__device__ int   g_idx[Bn];
__device__ int   g_frows[Bn];
__device__ int   g_nflag;

typedef unsigned long long ull;

// ---------------------------------------------------------------------------
// helpers (baseline ISA only)
// ---------------------------------------------------------------------------
__device__ __forceinline__ unsigned smem_u32(const void* p) {
    unsigned a;
    asm("{ .reg .u64 t; cvta.to.shared.u64 t, %1; cvt.u32.u64 %0, t; }"
        : "=r"(a) : "l"(p));
    return a;
}
__device__ __forceinline__ void cp16(unsigned dst, const void* src) {
    asm volatile("cp.async.cg.shared.global [%0], [%1], 16;"
                 :: "r"(dst), "l"(src) : "memory");
}
__device__ __forceinline__ void cp_commit() {
    asm volatile("cp.async.commit_group;" ::: "memory");
}
__device__ __forceinline__ void cp_wait1() {
    asm volatile("cp.async.wait_group 1;" ::: "memory");
}
__device__ __forceinline__ void cp_wait0() {
    asm volatile("cp.async.wait_group 0;" ::: "memory");
}
__device__ __forceinline__ void ldsm4(unsigned* r, unsigned a) {
    asm volatile("ldmatrix.sync.aligned.m8n8.x4.shared.b16 {%0,%1,%2,%3}, [%4];"
                 : "=r"(r[0]), "=r"(r[1]), "=r"(r[2]), "=r"(r[3]) : "r"(a));
}
__device__ __forceinline__ void mma_tf32(float* c, const unsigned* a,
                                         const unsigned* b) {
    asm volatile(
        "mma.sync.aligned.m16n8k8.row.col.f32.tf32.tf32.f32 "
        "{%0,%1,%2,%3}, {%4,%5,%6,%7}, {%8,%9}, {%0,%1,%2,%3};"
        : "+f"(c[0]), "+f"(c[1]), "+f"(c[2]), "+f"(c[3])
        : "r"(a[0]), "r"(a[1]), "r"(a[2]), "r"(a[3]), "r"(b[0]), "r"(b[1]));
}
__device__ __forceinline__ void upk(ull v, float& a, float& b) {
    asm("mov.b64 {%0,%1}, %2;" : "=f"(a), "=f"(b) : "l"(v));
}
__device__ __forceinline__ void ffma2(ull& acc, ull x, ull w) {
    asm("fma.rn.f32x2 %0, %1, %2, %0;" : "+l"(acc) : "l"(x), "l"(w));
}
// order-preserving float->uint, code in low 32 (lower index wins ties)
__device__ __forceinline__ ull packdi(float d, int c) {
    unsigned u = __float_as_uint(d);
    u = (u & 0x80000000u) ? ~u : (u | 0x80000000u);
    return ((ull)u << 32) | (unsigned)c;
}
__device__ __forceinline__ float unpackd(ull p) {
    unsigned u = (unsigned)(p >> 32);
    u = (u & 0x80000000u) ? (u ^ 0x80000000u) : ~u;
    return __uint_as_float(u);
}

// ---------------------------------------------------------------------------
// prep: zero histogram + flag counter, compute sum(W^2) per code
// ---------------------------------------------------------------------------
__global__ void vq_prep(const float* __restrict__ W) {
    int g = blockIdx.x * blockDim.x + threadIdx.x;
    int code = g >> 4;
    int l = g & 15;
    const float* wr = W + (size_t)code * Dn + l * 16;
    float s = 0.f;
#pragma unroll
    for (int t = 0; t < 16; t++) { float v = wr[t]; s += v * v; }
#pragma unroll
    for (int o = 8; o; o >>= 1) s += __shfl_xor_sync(0xffffffffu, s, o, 16);
    if (l == 0) g_sw[code] = s;
    if (g < Kn) g_counts[g] = 0;
    if (g == 0) g_nflag = 0;
}

// ---------------------------------------------------------------------------
// main: tf32 mma.sync distance GEMM; per-row top-2; flag rows with small gap
// 8 warps = 4(m) x 2(n); warp tile m32 x n32; ldmatrix-fed; no epilogue I/O
// ---------------------------------------------------------------------------
__global__ __launch_bounds__(256, 1)
void vq_main(const float* __restrict__ X, const float* __restrict__ W) {
    extern __shared__ char smem[];
    float* sws  = (float*)(smem + OFF_SW);
    ull*   bst1 = (ull*)(smem + OFF_B1);
    ull*   bst2 = (ull*)(smem + OFF_B2);
    const unsigned sb = smem_u32(smem);

    const int tid  = threadIdx.x;
    const int wid  = tid >> 5;
    const int lane = tid & 31;
    const int qid  = lane >> 2;
    const int lq   = lane & 3;
    const int g    = lane >> 3;       // ldmatrix pointer group
    const int jj   = lane & 7;
    const int wm   = wid & 3;
    const int wn   = wid >> 2;
    const int R0   = blockIdx.x * ROWS;

    if (tid < ROWS) { bst1[tid] = ~0ull; bst2[tid] = ~0ull; }
    for (int c = tid; c < Kn; c += 256) sws[c] = g_sw[c];

    // X tile -> smem (async), 8192 x 16B, stride 260 floats
#pragma unroll
    for (int j = 0; j < 32; j++) {
        int q = tid + 256 * j;
        int r = q >> 6, sg = q & 63;
        cp16(sb + OFF_XS + (r * XS_STR + 4 * sg) * 4,
             X + (size_t)(R0 + r) * Dn + 4 * sg);
    }
    cp_commit();
    // chunk 0 (ntile 0, khalf 0): 64 codes x 128 dims
#pragma unroll
    for (int j = 0; j < 8; j++) {
        int q = tid + 256 * j;
        int r = q >> 5, sg = q & 31;
        cp16(sb + OFF_B + (r * BS_STR + 4 * sg) * 4,
             W + (size_t)r * Dn + 4 * sg);
    }
    cp_commit();
    cp_wait1();
    __syncthreads();

    // per-thread ldmatrix tile offsets (bytes, within tiles)
    const unsigned aO0 = ((32 * wm + ((g & 1) << 3) + jj) * XS_STR
                          + ((g >> 1) << 2)) * 4;
    const unsigned aO1 = aO0 + 16 * XS_STR * 4;
    const unsigned bO0 = ((32 * wn + ((g >> 1) << 3) + jj) * BS_STR
                          + ((g & 1) << 2)) * 4;
    const unsigned bO1 = bO0 + 16 * BS_STR * 4;

    float acc[2][4][4];
#pragma unroll
    for (int mi = 0; mi < 2; mi++)
#pragma unroll
        for (int nj = 0; nj < 4; nj++)
#pragma unroll
            for (int t = 0; t < 4; t++) acc[mi][nj][t] = 0.f;

    ull p1[2][2], p2[2][2];
#pragma unroll
    for (int mi = 0; mi < 2; mi++)
#pragma unroll
        for (int fr = 0; fr < 2; fr++) { p1[mi][fr] = ~0ull; p2[mi][fr] = ~0ull; }

    for (int i = 0; i < NCHUNKS; ++i) {
        if (i + 1 < NCHUNKS) {
            int ni = i + 1, nt = ni >> 1, kh = ni & 1;
            const float* wsrc = W + (size_t)(nt * NTILE) * Dn + kh * 128;
            unsigned bdst = sb + OFF_B + (ni & 1) * B_BYTES;
#pragma unroll
            for (int j = 0; j < 8; j++) {
                int q = tid + 256 * j;
                int r = q >> 5, sg = q & 31;
                cp16(bdst + (r * BS_STR + 4 * sg) * 4,
                     wsrc + (size_t)r * Dn + 4 * sg);
            }
            cp_commit();
            cp_wait1();
        } else {
            cp_wait0();
        }
        __syncthreads();

        const int khalf = i & 1;
        const unsigned xA = sb + OFF_XS + khalf * 512;      // +128 floats
        const unsigned bA = sb + OFF_B + (i & 1) * B_BYTES;

#pragma unroll 4
        for (int kk = 0; kk < 16; kk++) {
            unsigned a0[4], a1[4], b0[4], b1[4];
            ldsm4(a0, xA + aO0 + kk * 32);
            ldsm4(a1, xA + aO1 + kk * 32);
            ldsm4(b0, bA + bO0 + kk * 32);
            ldsm4(b1, bA + bO1 + kk * 32);
            mma_tf32(acc[0][0], a0, b0);
            mma_tf32(acc[0][1], a0, b0 + 2);
            mma_tf32(acc[0][2], a0, b1);
            mma_tf32(acc[0][3], a0, b1 + 2);
            mma_tf32(acc[1][0], a1, b0);
            mma_tf32(acc[1][1], a1, b0 + 2);
            mma_tf32(acc[1][2], a1, b1);
            mma_tf32(acc[1][3], a1, b1 + 2);
        }

        if (khalf == 1) {             // n-tile complete: fold into top-2
            int ntile = i >> 1;
#pragma unroll
            for (int mi = 0; mi < 2; mi++)
#pragma unroll
                for (int nj = 0; nj < 4; nj++) {
                    int c0 = ntile * NTILE + wn * 32 + nj * 8 + 2 * lq;
#pragma unroll
                    for (int fr = 0; fr < 2; fr++) {
#pragma unroll
                        for (int cc = 0; cc < 2; cc++) {
                            float d = sws[c0 + cc]
                                      - 2.0f * acc[mi][nj][fr * 2 + cc];
                            ull p = packdi(d, c0 + cc);
                            if (p < p1[mi][fr]) { p2[mi][fr] = p1[mi][fr]; p1[mi][fr] = p; }
                            else if (p < p2[mi][fr]) { p2[mi][fr] = p; }
                        }
                        acc[mi][nj][fr * 2]     = 0.f;
                        acc[mi][nj][fr * 2 + 1] = 0.f;
                    }
                }
        }
        __syncthreads();
    }

    // quad-merge top-2 (lanes lq 0..3 share a row-slot), then two-phase atomicMin
    // (all shuffles unconditional: every thread of every warp participates)
#pragma unroll
    for (int mi = 0; mi < 2; mi++)
#pragma unroll
        for (int fr = 0; fr < 2; fr++) {
#pragma unroll
            for (int off = 1; off <= 2; off <<= 1) {
                ull q1 = __shfl_xor_sync(0xffffffffu, p1[mi][fr], off, 4);
                ull q2 = __shfl_xor_sync(0xffffffffu, p2[mi][fr], off, 4);
                if (q1 < p1[mi][fr]) {
                    p2[mi][fr] = (p1[mi][fr] < q2) ? p1[mi][fr] : q2;
                    p1[mi][fr] = q1;
                } else {
                    if (q1 < p2[mi][fr]) p2[mi][fr] = q1;
                }
            }
            if (lq == 0) {
                int row = 32 * wm + 16 * mi + 8 * fr + qid;
                atomicMin(&bst1[row], p1[mi][fr]);
            }
        }
    __syncthreads();
#pragma unroll
    for (int mi = 0; mi < 2; mi++)
#pragma unroll
        for (int fr = 0; fr < 2; fr++) {
            if (lq == 0) {
                int row = 32 * wm + 16 * mi + 8 * fr + qid;
                ull cand = (p1[mi][fr] == bst1[row]) ? p2[mi][fr] : p1[mi][fr];
                atomicMin(&bst2[row], cand);
            }
        }
    __syncthreads();

    if (tid < ROWS) {
        int gRow = R0 + tid;
        ull b1 = bst1[tid];
        g_idx[gRow] = (int)(b1 & 0xFFFFFFFFull);
        float d1 = unpackd(b1);
        float d2 = unpackd(bst2[tid]);
        if (d2 - d1 < TAU) {
            int s = atomicAdd(&g_nflag, 1);
            g_frows[s] = gRow;
        }
    }
}

// ---------------------------------------------------------------------------
// fallback: exact fp32 re-rank of all 1024 codes for flagged rows
// block = 32 rows; W streamed through smem in 64-code chunks
// ---------------------------------------------------------------------------
__global__ __launch_bounds__(256, 1)
void vq_fallback(const float* __restrict__ X, const float* __restrict__ W) {
    extern __shared__ char smem[];
    float* sws = (float*)(smem + FB_SW);
    float* sxs = (float*)(smem + FB_SX);
    int*   rid = (int*)(smem + FB_RID);

    const int tid = threadIdx.x;
    int n = g_nflag;
    int base = blockIdx.x * FB_ROWS;
    if (base >= n) return;                      // uniform per block
    int cnt = min(FB_ROWS, n - base);

    if (tid < cnt) rid[tid] = g_frows[base + tid];
    for (int c = tid; c < Kn; c += 256) sws[c] = g_sw[c];
    // zero X smem so rows >= cnt hold benign data (no guarded shuffles needed)
#pragma unroll
    for (int j = 0; j < 8; j++) {
        int q = tid + 256 * j;
        *(float4*)(smem + FB_XS + ((q >> 6) * 260 + 4 * (q & 63)) * 4) =
            make_float4(0.f, 0.f, 0.f, 0.f);
    }
    __syncthreads();

    // load flagged x rows (stride 260 floats, float4-aligned)
#pragma unroll
    for (int j = 0; j < 8; j++) {
        int q = tid + 256 * j;
        int r = q >> 6, sg = q & 63;
        if (r < cnt) {
            float4 v = *(const float4*)(X + (size_t)rid[r] * Dn + 4 * sg);
            *(float4*)(smem + FB_XS + (r * 260 + 4 * sg) * 4) = v;
        }
    }
    __syncthreads();

    // sum(x^2) per row. NOTE: shuffle is UNCONDITIONAL for every thread of
    // every warp (the R10 deadlock was a divergent __shfl_xor_sync here).
    {
        int l = tid & 15;
        int rr0 = tid >> 4;                     // 0..15
#pragma unroll
        for (int it = 0; it < 2; it++) {
            int rr = rr0 + 16 * it;             // 0..31, always valid smem
            const float* xr = (const float*)(smem + FB_XS + rr * 1040) + 16 * l;
            float s = 0.f;
#pragma unroll
            for (int t = 0; t < 16; t++) s += xr[t] * xr[t];
#pragma unroll
            for (int o = 8; o; o >>= 1)
                s += __shfl_xor_sync(0xffffffffu, s, o, 16);
            if (l == 0) sxs[rr] = s;            // rows >= cnt: harmless zeros
        }
    }

    const int myrow = tid >> 3;
    const int cg    = tid & 7;
    const char* xrow = smem + FB_XS + myrow * 1040;
    ull best = ~0ull;

    for (int ch = 0; ch < Kn / 64; ++ch) {
        __syncthreads();                       // prior chunk readers done
        // load 64-code chunk (full 256 dims, stride 260)
#pragma unroll
        for (int j = 0; j < 16; j++) {
            int q = tid + 256 * j;
            int r = q >> 6, sg = q & 63;
            float4 v = *(const float4*)(W + (size_t)(ch * 64 + r) * Dn + 4 * sg);
            *(float4*)(smem + FB_WS + (r * 260 + 4 * sg) * 4) = v;
        }
        __syncthreads();

        if (myrow < cnt) {
            ull accA[8], accB[8];
#pragma unroll
            for (int t = 0; t < 8; t++) { accA[t] = 0ull; accB[t] = 0ull; }
            const char* wr[8];
#pragma unroll
            for (int t = 0; t < 8; t++)
                wr[t] = smem + FB_WS + (8 * t + cg) * 1040;
#pragma unroll 8
            for (int dps = 0; dps < 64; dps++) {
                ulonglong2 xq = *(const ulonglong2*)(xrow + dps * 16);
#pragma unroll
                for (int t = 0; t < 8; t++) {
                    ulonglong2 wq = *(const ulonglong2*)(wr[t] + dps * 16);
                    ffma2(accA[t], xq.x, wq.x);
                    ffma2(accB[t], xq.y, wq.y);
                }
            }
#pragma unroll
            for (int t = 0; t < 8; t++) {
                float a, b, c, d;
                upk(accA[t], a, b);
                upk(accB[t], c, d);
                float dot = (a + b) + (c + d);
                int code = ch * 64 + 8 * t + cg;
                float dist = (sxs[myrow] + sws[code]) - 2.0f * dot;
                ull p = packdi(dist, code);
                if (p < best) best = p;
            }
        }
    }

    // reduce across the 8 threads of a row (unconditional shuffles)
#pragma unroll
    for (int off = 1; off <= 4; off <<= 1) {
        ull o = __shfl_xor_sync(0xffffffffu, best, off, 8);
        if (o < best) best = o;
    }
    if (cg == 0 && myrow < cnt)
        g_idx[rid[myrow]] = (int)(best & 0xFFFFFFFFull);
}

// ---------------------------------------------------------------------------
// epilogue: out = x + (W[idx]-x); histogram; deterministic loss partials
// ---------------------------------------------------------------------------
__global__ __launch_bounds__(256, 1)
void vq_epilogue(const float* __restrict__ X, const float* __restrict__ W,
                 float* __restrict__ out) {
    __shared__ float red[8];
    const int tid = threadIdx.x;
    const int R0 = blockIdx.x * ROWS;

    if (tid < ROWS) atomicAdd(&g_counts[g_idx[R0 + tid]], 1);

    float lsum = 0.f;
    for (int r = 0; r < ROWS; ++r) {
        int   wi = g_idx[R0 + r];
        float xv = X[(size_t)(R0 + r) * Dn + tid];
        float wv = W[(size_t)wi * Dn + tid];
        float dq = wv - xv;
        out[(size_t)(R0 + r) * Dn + tid] = xv + dq;
        lsum += dq * dq;
    }
#pragma unroll
    for (int o = 16; o; o >>= 1) lsum += __shfl_xor_sync(0xffffffffu, lsum, o);
    if ((tid & 31) == 0) red[tid >> 5] = lsum;
    __syncthreads();
    if (tid == 0) {
        float s = 0.f;
#pragma unroll
        for (int w = 0; w < 8; w++) s += red[w];
        g_partial[blockIdx.x] = s;
    }
}

// ---------------------------------------------------------------------------
// final: reduce loss partials (double), entropy -> perplexity
// ---------------------------------------------------------------------------
__global__ void vq_final(float* __restrict__ out, long long out_size) {
    __shared__ double sd[512];
    int tid = threadIdx.x;  // 512 threads

    double s = (double)g_partial[tid];  // NBLK == 512
    double e = 0.0;
    for (int c = tid; c < Kn; c += 512) {
        double p = (double)g_counts[c] / 65536.0;
        e += p * log(p + 1e-10);
    }

    sd[tid] = s;
    __syncthreads();
    for (int o = 256; o; o >>= 1) { if (tid < o) sd[tid] += sd[tid + o]; __syncthreads(); }
    double tot = sd[0];
    __syncthreads();
    sd[tid] = e;
    __syncthreads();
    for (int o = 256; o; o >>= 1) { if (tid < o) sd[tid] += sd[tid + o]; __syncthreads(); }

    if (tid == 0 && out_size >= (long long)Bn * Dn + 2) {
        double m = tot / ((double)Bn * (double)Dn);
        float mf = (float)m;
        float loss = mf + 0.25f * mf;
        out[(size_t)Bn * Dn]     = loss;
        out[(size_t)Bn * Dn + 1] = (float)exp(-sd[0]);
    }
}

// ---------------------------------------------------------------------------
extern "C" void kernel_launch(void* const* d_in, const int* in_sizes, int n_in,
                              void* d_out, int out_size) {
    const float* A  = (const float*)d_in[0];
    const float* Bp = (const float*)d_in[1];
    const float* X;
    const float* W;
    if (in_sizes[0] == Bn * Dn) { X = A;  W = Bp; }
    else                        { X = Bp; W = A;  }
    float* out = (float*)d_out;

    cudaFuncSetAttribute(vq_main, cudaFuncAttributeMaxDynamicSharedMemorySize,
                         SMEM_MAIN);
    cudaFuncSetAttribute(vq_fallback, cudaFuncAttributeMaxDynamicSharedMemorySize,
                         SMEM_FB);

    vq_prep<<<64, 256>>>(W);
    vq_main<<<NBLK, 256, SMEM_MAIN>>>(X, W);
    vq_fallback<<<Bn / FB_ROWS, 256, SMEM_FB>>>(X, W);
    vq_epilogue<<<NBLK, 256>>>(X, W, out);
    vq_final<<<1, 512>>>(out, (long long)out_size);
}

// round 15
// speedup vs baseline: 2.5569x; 2.1417x over previous
#include <cuda_runtime.h>
#include <cuda_fp16.h>
#include <math.h>

// Problem constants
#define Bn 65536
#define Dn 256
#define Kn 1024

#define ROWS 128                 // rows (M) per CTA
#define NBLK (Bn / ROWS)         // 512 CTAs
#define NTILE 64                 // codes per n-tile
#define NCHUNKS 32               // 16 n-tiles x 2 k-halves
#define XS_STRH 264              // halfs: X row stride (528B, conflict-free ldsm)
#define BS_STRH 136              // halfs: B chunk row stride (272B)
#define TAU 4e-4f                // ~100-sigma fp16-GEMM noise + ref-rounding margin

// vq_main smem offsets (bytes)
#define OFF_XS 0
#define XS_BYTES (ROWS * XS_STRH * 2)           // 67584
#define OFF_B  XS_BYTES
#define B_BYTES (NTILE * BS_STRH * 2)           // 17408 per buffer
#define OFF_SW (OFF_B + 2 * B_BYTES)            // 102400
#define OFF_B1 (OFF_SW + 4096)                  // 106496 (128 ull)
#define OFF_B2 (OFF_B1 + 1024)                  // 107520 (128 ull)
#define SMEM_MAIN (OFF_B2 + 1024)               // 108544  -> 2 CTAs/SM

// vq_fallback smem offsets (unchanged, proven)
#define FB_ROWS 32
#define FB_XS 0
#define FB_WS 33280
#define FB_SW 99840
#define FB_SX 103936
#define FB_RID 104064
#define SMEM_FB 104192

// Scratch (no allocations allowed)
__device__ float  g_sw[Kn];
__device__ int    g_counts[Kn];
__device__ float  g_partial[NBLK];
__device__ int    g_idx[Bn];
__device__ int    g_frows[Bn];
__device__ int    g_nflag;
__device__ __half g_xh[(size_t)Bn * Dn];   // fp16 copy of X (rna)
__device__ __half g_wh[Kn * Dn];           // fp16 copy of W (rna)

typedef unsigned long long ull;

// ---------------------------------------------------------------------------
// helpers (baseline ISA only)
// ---------------------------------------------------------------------------
__device__ __forceinline__ unsigned smem_u32(const void* p) {
    unsigned a;
    asm("{ .reg .u64 t; cvta.to.shared.u64 t, %1; cvt.u32.u64 %0, t; }"
        : "=r"(a) : "l"(p));
    return a;
}
__device__ __forceinline__ void cp16(unsigned dst, const void* src) {
    asm volatile("cp.async.cg.shared.global [%0], [%1], 16;"
                 :: "r"(dst), "l"(src) : "memory");
}
__device__ __forceinline__ void cp_commit() {
    asm volatile("cp.async.commit_group;" ::: "memory");
}
__device__ __forceinline__ void cp_wait1() {
    asm volatile("cp.async.wait_group 1;" ::: "memory");
}
__device__ __forceinline__ void cp_wait0() {
    asm volatile("cp.async.wait_group 0;" ::: "memory");
}
__device__ __forceinline__ void ldsm4(unsigned* r, unsigned a) {
    asm volatile("ldmatrix.sync.aligned.m8n8.x4.shared.b16 {%0,%1,%2,%3}, [%4];"
                 : "=r"(r[0]), "=r"(r[1]), "=r"(r[2]), "=r"(r[3]) : "r"(a));
}
__device__ __forceinline__ void mma_f16(float* c, const unsigned* a,
                                        const unsigned* b) {
    asm volatile(
        "mma.sync.aligned.m16n8k16.row.col.f32.f16.f16.f32 "
        "{%0,%1,%2,%3}, {%4,%5,%6,%7}, {%8,%9}, {%0,%1,%2,%3};"
        : "+f"(c[0]), "+f"(c[1]), "+f"(c[2]), "+f"(c[3])
        : "r"(a[0]), "r"(a[1]), "r"(a[2]), "r"(a[3]), "r"(b[0]), "r"(b[1]));
}
__device__ __forceinline__ void upk(ull v, float& a, float& b) {
    asm("mov.b64 {%0,%1}, %2;" : "=f"(a), "=f"(b) : "l"(v));
}
__device__ __forceinline__ void ffma2(ull& acc, ull x, ull w) {
    asm("fma.rn.f32x2 %0, %1, %2, %0;" : "+l"(acc) : "l"(x), "l"(w));
}
// order-preserving float->uint, code in low 32 (lower index wins ties)
__device__ __forceinline__ ull packdi(float d, int c) {
    unsigned u = __float_as_uint(d);
    u = (u & 0x80000000u) ? ~u : (u | 0x80000000u);
    return ((ull)u << 32) | (unsigned)c;
}
__device__ __forceinline__ float unpackd(ull p) {
    unsigned u = (unsigned)(p >> 32);
    u = (u & 0x80000000u) ? (u ^ 0x80000000u) : ~u;
    return __uint_as_float(u);
}

// ---------------------------------------------------------------------------
// prep: zero histogram + flag counter, sum(W^2) per code, W -> fp16 (rna)
// ---------------------------------------------------------------------------
__global__ void vq_prep(const float* __restrict__ W) {
    int g = blockIdx.x * blockDim.x + threadIdx.x;
    int code = g >> 4;
    int l = g & 15;
    const float* wr = W + (size_t)code * Dn + l * 16;
    __half* wh = g_wh + (size_t)code * Dn + l * 16;
    float s = 0.f;
#pragma unroll
    for (int t = 0; t < 16; t++) {
        float v = wr[t];
        s += v * v;
        wh[t] = __float2half_rn(v);
    }
#pragma unroll
    for (int o = 8; o; o >>= 1) s += __shfl_xor_sync(0xffffffffu, s, o, 16);
    if (l == 0) g_sw[code] = s;
    if (g < Kn) g_counts[g] = 0;
    if (g == 0) g_nflag = 0;
}

// X -> fp16 (rna), vectorized
__global__ void vq_cvtx(const float* __restrict__ X) {
    size_t i = (size_t)(blockIdx.x * blockDim.x + threadIdx.x) * 4;
    float4 v = *(const float4*)(X + i);
    __half2* d = (__half2*)(g_xh + i);
    d[0] = __floats2half2_rn(v.x, v.y);
    d[1] = __floats2half2_rn(v.z, v.w);
}

// ---------------------------------------------------------------------------
// main: fp16 m16n8k16 mma.sync distance GEMM; per-row top-2; flag small gaps
// 8 warps = 4(m) x 2(n); warp tile m32 x n32; 2 CTAs/SM (108.5 KB smem)
// ---------------------------------------------------------------------------
__global__ __launch_bounds__(256, 2)
void vq_main() {
    extern __shared__ char smem[];
    float* sws  = (float*)(smem + OFF_SW);
    ull*   bst1 = (ull*)(smem + OFF_B1);
    ull*   bst2 = (ull*)(smem + OFF_B2);
    const unsigned sb = smem_u32(smem);

    const int tid  = threadIdx.x;
    const int wid  = tid >> 5;
    const int lane = tid & 31;
    const int qid  = lane >> 2;
    const int lq   = lane & 3;
    const int g    = lane >> 3;       // ldmatrix pointer group
    const int jj   = lane & 7;
    const int wm   = wid & 3;         // m-warp 0..3 (32 rows each)
    const int wn   = wid >> 2;        // n-warp 0..1 (32 codes each)
    const int R0   = blockIdx.x * ROWS;

    if (tid < ROWS) { bst1[tid] = ~0ull; bst2[tid] = ~0ull; }
    for (int c = tid; c < Kn; c += 256) sws[c] = g_sw[c];

    // X tile (fp16) -> smem: 4096 x 16B, row = 512B over stride 528B
#pragma unroll
    for (int j = 0; j < 16; j++) {
        int q = tid + 256 * j;
        int r = q >> 5, sg = q & 31;
        cp16(sb + OFF_XS + r * (XS_STRH * 2) + sg * 16,
             g_xh + (size_t)(R0 + r) * Dn + sg * 8);
    }
    cp_commit();
    // chunk 0 (ntile 0, khalf 0): 64 codes x 128 halfs = 1024 x 16B
#pragma unroll
    for (int j = 0; j < 4; j++) {
        int q = tid + 256 * j;
        int r = q >> 4, sg = q & 15;
        cp16(sb + OFF_B + r * (BS_STRH * 2) + sg * 16,
             g_wh + (size_t)r * Dn + sg * 8);
    }
    cp_commit();
    cp_wait1();                       // X landed
    __syncthreads();

    // ldmatrix offsets (bytes within tiles), m16n8k16 fragment mapping:
    // A x4: m0 rows r..r+7 k0-7 | m1 rows+8 k0-7 | m2 rows k8-15 | m3 rows+8 k8-15
    const unsigned aO0 = (32 * wm + ((g & 1) << 3) + jj) * (XS_STRH * 2)
                         + ((g >> 1) << 4);
    const unsigned aO1 = aO0 + 16 * (XS_STRH * 2);
    // B x4: m0 codes c..c+7 k0-7 | m1 codes k8-15 | m2 codes+8 k0-7 | m3 +8 k8-15
    const unsigned bO0 = (32 * wn + ((g >> 1) << 3) + jj) * (BS_STRH * 2)
                         + ((g & 1) << 4);
    const unsigned bO1 = bO0 + 16 * (BS_STRH * 2);

    float acc[2][4][4];
#pragma unroll
    for (int mi = 0; mi < 2; mi++)
#pragma unroll
        for (int nj = 0; nj < 4; nj++)
#pragma unroll
            for (int t = 0; t < 4; t++) acc[mi][nj][t] = 0.f;

    ull p1[2][2], p2[2][2];
#pragma unroll
    for (int mi = 0; mi < 2; mi++)
#pragma unroll
        for (int fr = 0; fr < 2; fr++) { p1[mi][fr] = ~0ull; p2[mi][fr] = ~0ull; }

    for (int i = 0; i < NCHUNKS; ++i) {
        if (i + 1 < NCHUNKS) {
            int ni = i + 1, nt = ni >> 1, kh = ni & 1;
            const __half* wsrc = g_wh + (size_t)(nt * NTILE) * Dn + kh * 128;
            unsigned bdst = sb + OFF_B + (ni & 1) * B_BYTES;
#pragma unroll
            for (int j = 0; j < 4; j++) {
                int q = tid + 256 * j;
                int r = q >> 4, sg = q & 15;
                cp16(bdst + r * (BS_STRH * 2) + sg * 16,
                     wsrc + (size_t)r * Dn + sg * 8);
            }
            cp_commit();
            cp_wait1();               // current chunk landed
        } else {
            cp_wait0();
        }
        __syncthreads();

        const int khalf = i & 1;
        const unsigned xA = sb + OFF_XS + khalf * 256;      // +128 halfs
        const unsigned bA = sb + OFF_B + (i & 1) * B_BYTES;

#pragma unroll 4
        for (int ks = 0; ks < 8; ks++) {                    // k16 steps
            unsigned a0[4], a1[4], b0[4], b1[4];
            ldsm4(a0, xA + aO0 + ks * 32);
            ldsm4(a1, xA + aO1 + ks * 32);
            ldsm4(b0, bA + bO0 + ks * 32);
            ldsm4(b1, bA + bO1 + ks * 32);
            mma_f16(acc[0][0], a0, b0);
            mma_f16(acc[0][1], a0, b0 + 2);
            mma_f16(acc[0][2], a0, b1);
            mma_f16(acc[0][3], a0, b1 + 2);
            mma_f16(acc[1][0], a1, b0);
            mma_f16(acc[1][1], a1, b0 + 2);
            mma_f16(acc[1][2], a1, b1);
            mma_f16(acc[1][3], a1, b1 + 2);
        }

        if (khalf == 1) {             // n-tile complete: fold into top-2
            int ntile = i >> 1;
#pragma unroll
            for (int mi = 0; mi < 2; mi++)
#pragma unroll
                for (int nj = 0; nj < 4; nj++) {
                    int c0 = ntile * NTILE + 32 * wn + 8 * nj + 2 * lq;
#pragma unroll
                    for (int fr = 0; fr < 2; fr++) {
#pragma unroll
                        for (int cc = 0; cc < 2; cc++) {
                            float d = sws[c0 + cc]
                                      - 2.0f * acc[mi][nj][fr * 2 + cc];
                            ull p = packdi(d, c0 + cc);
                            if (p < p1[mi][fr]) { p2[mi][fr] = p1[mi][fr]; p1[mi][fr] = p; }
                            else if (p < p2[mi][fr]) { p2[mi][fr] = p; }
                        }
                        acc[mi][nj][fr * 2]     = 0.f;
                        acc[mi][nj][fr * 2 + 1] = 0.f;
                    }
                }
        }
        __syncthreads();
    }

    // quad-merge top-2, then two-phase atomicMin (all shuffles unconditional)
#pragma unroll
    for (int mi = 0; mi < 2; mi++)
#pragma unroll
        for (int fr = 0; fr < 2; fr++) {
#pragma unroll
            for (int off = 1; off <= 2; off <<= 1) {
                ull q1 = __shfl_xor_sync(0xffffffffu, p1[mi][fr], off, 4);
                ull q2 = __shfl_xor_sync(0xffffffffu, p2[mi][fr], off, 4);
                if (q1 < p1[mi][fr]) {
                    p2[mi][fr] = (p1[mi][fr] < q2) ? p1[mi][fr] : q2;
                    p1[mi][fr] = q1;
                } else {
                    if (q1 < p2[mi][fr]) p2[mi][fr] = q1;
                }
            }
            if (lq == 0) {
                int row = 32 * wm + 16 * mi + 8 * fr + qid;
                atomicMin(&bst1[row], p1[mi][fr]);
            }
        }
    __syncthreads();
#pragma unroll
    for (int mi = 0; mi < 2; mi++)
#pragma unroll
        for (int fr = 0; fr < 2; fr++) {
            if (lq == 0) {
                int row = 32 * wm + 16 * mi + 8 * fr + qid;
                ull cand = (p1[mi][fr] == bst1[row]) ? p2[mi][fr] : p1[mi][fr];
                atomicMin(&bst2[row], cand);
            }
        }
    __syncthreads();

    if (tid < ROWS) {
        int gRow = R0 + tid;
        ull b1 = bst1[tid];
        g_idx[gRow] = (int)(b1 & 0xFFFFFFFFull);
        float d1 = unpackd(b1);
        float d2 = unpackd(bst2[tid]);
        if (d2 - d1 < TAU) {
            int s = atomicAdd(&g_nflag, 1);
            g_frows[s] = gRow;
        }
    }
}

// ---------------------------------------------------------------------------
// fallback: exact fp32 re-rank of all 1024 codes for flagged rows (proven)
// ---------------------------------------------------------------------------
__global__ __launch_bounds__(256, 1)
void vq_fallback(const float* __restrict__ X, const float* __restrict__ W) {
    extern __shared__ char smem[];
    float* sws = (float*)(smem + FB_SW);
    float* sxs = (float*)(smem + FB_SX);
    int*   rid = (int*)(smem + FB_RID);

    const int tid = threadIdx.x;
    int n = g_nflag;
    int base = blockIdx.x * FB_ROWS;
    if (base >= n) return;                      // uniform per block
    int cnt = min(FB_ROWS, n - base);

    if (tid < cnt) rid[tid] = g_frows[base + tid];
    for (int c = tid; c < Kn; c += 256) sws[c] = g_sw[c];
#pragma unroll
    for (int j = 0; j < 8; j++) {               // zero X smem (benign tail rows)
        int q = tid + 256 * j;
        *(float4*)(smem + FB_XS + ((q >> 6) * 260 + 4 * (q & 63)) * 4) =
            make_float4(0.f, 0.f, 0.f, 0.f);
    }
    __syncthreads();

#pragma unroll
    for (int j = 0; j < 8; j++) {
        int q = tid + 256 * j;
        int r = q >> 6, sg = q & 63;
        if (r < cnt) {
            float4 v = *(const float4*)(X + (size_t)rid[r] * Dn + 4 * sg);
            *(float4*)(smem + FB_XS + (r * 260 + 4 * sg) * 4) = v;
        }
    }
    __syncthreads();

    // sum(x^2) per row — shuffles UNCONDITIONAL (R10 deadlock lesson)
    {
        int l = tid & 15;
        int rr0 = tid >> 4;
#pragma unroll
        for (int it = 0; it < 2; it++) {
            int rr = rr0 + 16 * it;
            const float* xr = (const float*)(smem + FB_XS + rr * 1040) + 16 * l;
            float s = 0.f;
#pragma unroll
            for (int t = 0; t < 16; t++) s += xr[t] * xr[t];
#pragma unroll
            for (int o = 8; o; o >>= 1)
                s += __shfl_xor_sync(0xffffffffu, s, o, 16);
            if (l == 0) sxs[rr] = s;
        }
    }

    const int myrow = tid >> 3;
    const int cg    = tid & 7;
    const char* xrow = smem + FB_XS + myrow * 1040;
    ull best = ~0ull;

    for (int ch = 0; ch < Kn / 64; ++ch) {
        __syncthreads();
#pragma unroll
        for (int j = 0; j < 16; j++) {
            int q = tid + 256 * j;
            int r = q >> 6, sg = q & 63;
            float4 v = *(const float4*)(W + (size_t)(ch * 64 + r) * Dn + 4 * sg);
            *(float4*)(smem + FB_WS + (r * 260 + 4 * sg) * 4) = v;
        }
        __syncthreads();

        if (myrow < cnt) {
            ull accA[8], accB[8];
#pragma unroll
            for (int t = 0; t < 8; t++) { accA[t] = 0ull; accB[t] = 0ull; }
            const char* wr[8];
#pragma unroll
            for (int t = 0; t < 8; t++)
                wr[t] = smem + FB_WS + (8 * t + cg) * 1040;
#pragma unroll 8
            for (int dps = 0; dps < 64; dps++) {
                ulonglong2 xq = *(const ulonglong2*)(xrow + dps * 16);
#pragma unroll
                for (int t = 0; t < 8; t++) {
                    ulonglong2 wq = *(const ulonglong2*)(wr[t] + dps * 16);
                    ffma2(accA[t], xq.x, wq.x);
                    ffma2(accB[t], xq.y, wq.y);
                }
            }
#pragma unroll
            for (int t = 0; t < 8; t++) {
                float a, b, c, d;
                upk(accA[t], a, b);
                upk(accB[t], c, d);
                float dot = (a + b) + (c + d);
                int code = ch * 64 + 8 * t + cg;
                float dist = (sxs[myrow] + sws[code]) - 2.0f * dot;
                ull p = packdi(dist, code);
                if (p < best) best = p;
            }
        }
    }

#pragma unroll
    for (int off = 1; off <= 4; off <<= 1) {
        ull o = __shfl_xor_sync(0xffffffffu, best, off, 8);
        if (o < best) best = o;
    }
    if (cg == 0 && myrow < cnt)
        g_idx[rid[myrow]] = (int)(best & 0xFFFFFFFFull);
}

// ---------------------------------------------------------------------------
// epilogue: out = x + (W[idx]-x); histogram; deterministic loss partials
// idx preloaded to smem; unroll-4 batched loads for MLP
// ---------------------------------------------------------------------------
__global__ __launch_bounds__(256, 1)
void vq_epilogue(const float* __restrict__ X, const float* __restrict__ W,
                 float* __restrict__ out) {
    __shared__ float red[8];
    __shared__ int sIdx[ROWS];
    const int tid = threadIdx.x;
    const int R0 = blockIdx.x * ROWS;

    if (tid < ROWS) {
        int ix = g_idx[R0 + tid];
        sIdx[tid] = ix;
        atomicAdd(&g_counts[ix], 1);
    }
    __syncthreads();

    float lsum = 0.f;
#pragma unroll 1
    for (int r = 0; r < ROWS; r += 4) {
        float xv[4], wv[4];
        int wi[4];
#pragma unroll
        for (int u = 0; u < 4; u++) wi[u] = sIdx[r + u];
#pragma unroll
        for (int u = 0; u < 4; u++)
            xv[u] = X[(size_t)(R0 + r + u) * Dn + tid];
#pragma unroll
        for (int u = 0; u < 4; u++)
            wv[u] = W[(size_t)wi[u] * Dn + tid];
#pragma unroll
        for (int u = 0; u < 4; u++) {
            float dq = wv[u] - xv[u];
            out[(size_t)(R0 + r + u) * Dn + tid] = xv[u] + dq;
            lsum += dq * dq;                    // same accumulation order as R11
        }
    }
#pragma unroll
    for (int o = 16; o; o >>= 1) lsum += __shfl_xor_sync(0xffffffffu, lsum, o);
    if ((tid & 31) == 0) red[tid >> 5] = lsum;
    __syncthreads();
    if (tid == 0) {
        float s = 0.f;
#pragma unroll
        for (int w = 0; w < 8; w++) s += red[w];
        g_partial[blockIdx.x] = s;
    }
}

// ---------------------------------------------------------------------------
// final: reduce loss partials (double), entropy -> perplexity
// ---------------------------------------------------------------------------
__global__ void vq_final(float* __restrict__ out, long long out_size) {
    __shared__ double sd[512];
    int tid = threadIdx.x;  // 512 threads

    double s = (double)g_partial[tid];  // NBLK == 512
    double e = 0.0;
    for (int c = tid; c < Kn; c += 512) {
        double p = (double)g_counts[c] / 65536.0;
        e += p * log(p + 1e-10);
    }

    sd[tid] = s;
    __syncthreads();
    for (int o = 256; o; o >>= 1) { if (tid < o) sd[tid] += sd[tid + o]; __syncthreads(); }
    double tot = sd[0];
    __syncthreads();
    sd[tid] = e;
    __syncthreads();
    for (int o = 256; o; o >>= 1) { if (tid < o) sd[tid] += sd[tid + o]; __syncthreads(); }

    if (tid == 0 && out_size >= (long long)Bn * Dn + 2) {
        double m = tot / ((double)Bn * (double)Dn);
        float mf = (float)m;
        float loss = mf + 0.25f * mf;
        out[(size_t)Bn * Dn]     = loss;
        out[(size_t)Bn * Dn + 1] = (float)exp(-sd[0]);
    }
}

// ---------------------------------------------------------------------------
extern "C" void kernel_launch(void* const* d_in, const int* in_sizes, int n_in,
                              void* d_out, int out_size) {
    const float* A  = (const float*)d_in[0];
    const float* Bp = (const float*)d_in[1];
    const float* X;
    const float* W;
    if (in_sizes[0] == Bn * Dn) { X = A;  W = Bp; }
    else                        { X = Bp; W = A;  }
    float* out = (float*)d_out;

    cudaFuncSetAttribute(vq_main, cudaFuncAttributeMaxDynamicSharedMemorySize,
                         SMEM_MAIN);
    cudaFuncSetAttribute(vq_fallback, cudaFuncAttributeMaxDynamicSharedMemorySize,
                         SMEM_FB);

    vq_prep<<<64, 256>>>(W);
    vq_cvtx<<<Bn * Dn / 4 / 256, 256>>>(X);
    vq_main<<<NBLK, 256, SMEM_MAIN>>>();
    vq_fallback<<<Bn / FB_ROWS, 256, SMEM_FB>>>(X, W);
    vq_epilogue<<<NBLK, 256>>>(X, W, out);
    vq_final<<<1, 512>>>(out, (long long)out_size);
}